// round 8
// baseline (speedup 1.0000x reference)
#include <cuda_runtime.h>

#define SEQ 4096
#define HID 1024
#define NLAYERS 4
#define SCTA 128         // CTAs per scan layer
#define GCTA 20          // CTAs per inter-layer matvec stage
#define CSTRIDE 32       // ints between counter slots (128B lines)
#define GOUT 2048        // outputs per G stage (Zu 1024 + Zr 1024)
#define OPC 103          // ceil(GOUT / GCTA)

// ---------------- device scratch ----------------
__device__ float g_Z0u[SEQ * HID];
__device__ float g_Z0r[SEQ * HID];
__device__ float g_Z0c[SEQ * HID];
__device__ float g_Zu[3][SEQ * HID];     // layer 1..3 shared term (u & c gates)
__device__ float g_Zr[3][SEQ * HID];     // layer 1..3 reset term
__device__ float g_H[NLAYERS][SEQ * HID];
__device__ int   g_hctr[NLAYERS][16 * CSTRIDE];
__device__ int   g_gctr[3][GCTA * CSTRIDE];

__global__ void reset_ctrs_kernel() {
    int i = blockIdx.x * blockDim.x + threadIdx.x;
    int nh = NLAYERS * 16 * CSTRIDE;
    int ng = 3 * GCTA * CSTRIDE;
    if (i < nh) ((int*)g_hctr)[i] = 0;
    if (i < ng) ((int*)g_gctr)[i] = 0;
}

// ---------------- memory helpers ----------------
__device__ __forceinline__ float4 ldcg4(const float* p) {
    float4 v;
    asm volatile("ld.global.cg.v4.f32 {%0,%1,%2,%3},[%4];"
                 : "=f"(v.x), "=f"(v.y), "=f"(v.z), "=f"(v.w) : "l"(p) : "memory");
    return v;
}
__device__ __forceinline__ float ldcgf(const float* p) {
    float v;
    asm volatile("ld.global.cg.f32 %0,[%1];" : "=f"(v) : "l"(p) : "memory");
    return v;
}
__device__ __forceinline__ void stcg(float* p, float v) {
    asm volatile("st.global.cg.f32 [%0],%1;" :: "l"(p), "f"(v) : "memory");
}
__device__ __forceinline__ int ldacq(const int* p) {
    int v;
    asm volatile("ld.acquire.gpu.global.s32 %0,[%1];" : "=r"(v) : "l"(p) : "memory");
    return v;
}
__device__ __forceinline__ void red_release_add(int* p, int v) {
    asm volatile("red.release.gpu.global.add.s32 [%0],%1;" :: "l"(p), "r"(v) : "memory");
}

typedef unsigned long long ull;
__device__ __forceinline__ ull pack2(float lo, float hi) {
    ull r; asm("mov.b64 %0,{%1,%2};" : "=l"(r) : "f"(lo), "f"(hi)); return r;
}
__device__ __forceinline__ ull fma2(ull a, ull b, ull c) {
    ull d; asm("fma.rn.f32x2 %0,%1,%2,%3;" : "=l"(d) : "l"(a), "l"(b), "l"(c)); return d;
}
__device__ __forceinline__ float sum2(ull v) {
    float lo, hi; asm("mov.b64 {%0,%1},%2;" : "=f"(lo), "=f"(hi) : "l"(v));
    return lo + hi;
}

// ---------------- fp32 SGEMM batch (layer-0 input projections) -------------
struct GemmJob { const float* A; const float* B; float* C; };
__global__ __launch_bounds__(256) void sgemm_nt_batch(GemmJob j0, GemmJob j1, GemmJob j2) {
    const GemmJob job = (blockIdx.z == 0) ? j0 : (blockIdx.z == 1) ? j1 : j2;
    const float* __restrict__ A = job.A;
    const float* __restrict__ B = job.B;
    float* __restrict__ C = job.C;
    const int K = HID, N = HID;
    __shared__ float As[8][128];
    __shared__ float Bs[8][128];
    const int tid = threadIdx.x;
    const int m0 = blockIdx.y * 128;
    const int n0 = blockIdx.x * 128;
    const int tx = tid & 15;
    const int ty = tid >> 4;
    const int lrow = tid >> 1;
    const int kp = (tid & 1) * 4;

    const float* Ap = A + (m0 + lrow) * K + kp;
    const float* Bp = B + (n0 + lrow) * K + kp;

    float acc[8][8];
#pragma unroll
    for (int i = 0; i < 8; i++)
#pragma unroll
        for (int j = 0; j < 8; j++) acc[i][j] = 0.f;

    for (int k0 = 0; k0 < K; k0 += 8) {
        float4 av = *(const float4*)(Ap + k0);
        float4 bv = *(const float4*)(Bp + k0);
        __syncthreads();
        As[kp + 0][lrow] = av.x; As[kp + 1][lrow] = av.y;
        As[kp + 2][lrow] = av.z; As[kp + 3][lrow] = av.w;
        Bs[kp + 0][lrow] = bv.x; Bs[kp + 1][lrow] = bv.y;
        Bs[kp + 2][lrow] = bv.z; Bs[kp + 3][lrow] = bv.w;
        __syncthreads();
#pragma unroll
        for (int kk = 0; kk < 8; kk++) {
            float a[8], b[8];
#pragma unroll
            for (int i = 0; i < 8; i++) a[i] = As[kk][ty * 8 + i];
#pragma unroll
            for (int j = 0; j < 8; j++) b[j] = Bs[kk][tx * 8 + j];
#pragma unroll
            for (int i = 0; i < 8; i++)
#pragma unroll
                for (int j = 0; j < 8; j++) acc[i][j] = fmaf(a[i], b[j], acc[i][j]);
        }
    }
#pragma unroll
    for (int i = 0; i < 8; i++) {
        float* Cp = C + (m0 + ty * 8 + i) * N + n0 + tx * 8;
#pragma unroll
        for (int j = 0; j < 8; j++) Cp[j] = acc[i][j];
    }
}

// ---------------- fused pipeline kernel ----------------
struct ScanArgs {
    const float *Wu, *Wr, *Wc, *Bu, *Br, *Bc, *Pu, *Pr, *Pc;
    float *H, *outf;
    int *hctr;            // own recurrence counters (16 slots)
    const int *gctr;      // upstream G counters (20 slots) or null for layer 0
};
struct GArgs {
    const float *Wa, *Wb;  // Uh[l-1], Uhr[l-1]
    const float *Hin;      // producer layer's H buffer
    float *Zu, *Zr;
    const int *hctr;       // producer scan counters (16 slots)
    int *gctr;             // own counters (20 slots)
};
struct MegaArgs { ScanArgs s[4]; GArgs g[3]; };

// GRU layer scan body (R7-proven structure + optional G-gate in warp 1)
__device__ __forceinline__ void scan_body(const ScanArgs a, int b, float (*sh)[HID]) {
    const int warp = threadIdx.x >> 5;
    const int lane = threadIdx.x & 31;
    const int j = (b << 3) + warp;
    int* const myctr = a.hctr + (b & 15) * CSTRIDE;

    ull wu2[16], wr2[16], wc2[16];
    const float* wub = a.Wu + j * HID;
    const float* wrb = a.Wr + j * HID;
    const float* wcb = a.Wc + j * HID;
#pragma unroll
    for (int i = 0; i < 8; i++) {
        const int k = i * 128 + lane * 4;
        float4 x = *(const float4*)(wub + k);
        float4 y = *(const float4*)(wrb + k);
        float4 z = *(const float4*)(wcb + k);
        wu2[2 * i] = pack2(x.x, x.y); wu2[2 * i + 1] = pack2(x.z, x.w);
        wr2[2 * i] = pack2(y.x, y.y); wr2[2 * i + 1] = pack2(y.z, y.w);
        wc2[2 * i] = pack2(z.x, z.y); wc2[2 * i + 1] = pack2(z.z, z.w);
    }
    const float bu = a.Bu[j], br = a.Br[j], bc = a.Bc[j];
    float hj = 0.f;

    for (int t = 0; t < SEQ; t++) {
        float* shrow = sh[t & 1];
        if (warp == 0) {
            if (t > 0) {
                if (lane < 16) {
                    const int tgt = t * 64;
                    while (ldacq(a.hctr + lane * CSTRIDE) < tgt) { }
                }
                __syncwarp();
                const float* hrow = a.H + (t - 1) * HID;
#pragma unroll
                for (int i = 0; i < 8; i++)
                    *(float4*)(shrow + i * 128 + lane * 4) = ldcg4(hrow + i * 128 + lane * 4);
            } else {
#pragma unroll
                for (int i = 0; i < 8; i++)
                    *(float4*)(shrow + i * 128 + lane * 4) = make_float4(0.f, 0.f, 0.f, 0.f);
            }
        } else if (warp == 1 && a.gctr) {
            // wait for upstream G to finish Z row t (8 arrivals per slot per step)
            if (lane < GCTA) {
                const int tgt = (t + 1) * 8;
                while (ldacq(a.gctr + lane * CSTRIDE) < tgt) { }
            }
            __syncwarp();
        }
        __syncthreads();   // row staged + Z row t published

        // Z reads AFTER the gate (cg: freshly produced by G, keep out of L1)
        const float zu = ldcgf(a.Pu + t * HID + j);
        const float zr = ldcgf(a.Pr + t * HID + j);
        const float zc = ldcgf(a.Pc + t * HID + j);

        ull au2 = 0, ar2 = 0, ac2 = 0;
#pragma unroll
        for (int i = 0; i < 8; i++) {
            float4 h4 = *(const float4*)(shrow + i * 128 + lane * 4);
            const ull h01 = pack2(h4.x, h4.y);
            const ull h23 = pack2(h4.z, h4.w);
            au2 = fma2(wu2[2 * i], h01, au2);
            ar2 = fma2(wr2[2 * i], h01, ar2);
            ac2 = fma2(wc2[2 * i], h01, ac2);
            au2 = fma2(wu2[2 * i + 1], h23, au2);
            ar2 = fma2(wr2[2 * i + 1], h23, ar2);
            ac2 = fma2(wc2[2 * i + 1], h23, ac2);
        }
        float au = sum2(au2), ar = sum2(ar2), ac = sum2(ac2);
#pragma unroll
        for (int off = 16; off > 0; off >>= 1) {
            au += __shfl_xor_sync(0xffffffffu, au, off);
            ar += __shfl_xor_sync(0xffffffffu, ar, off);
            ac += __shfl_xor_sync(0xffffffffu, ac, off);
        }
        const float u = 1.f / (1.f + __expf(-(au + zu + bu)));
        const float r = 1.f / (1.f + __expf(-(ar + zr + br)));
        const float c = 1.f / (1.f + __expf(-(zc + r * ac + bc)));
        const float hn = fmaf(u, hj - c, c);
        hj = hn;

        if (lane == 0) {
            stcg(a.H + t * HID + j, hn);
            red_release_add(myctr, 1);
        }
    }
    if (lane == 0) a.outf[j] = hj;
}

// Inter-layer streaming matvec: Z(t) = [Uh; Uhr] @ h_prev(t), row by row
__device__ __forceinline__ void g_body(const GArgs a, int c, float (*sh)[HID]) {
    const int warp = threadIdx.x >> 5;
    const int lane = threadIdx.x & 31;
    const int o0 = c * OPC;
    const int o1 = (o0 + OPC < GOUT) ? o0 + OPC : GOUT;
    int* const myctr = a.gctr + c * CSTRIDE;

    for (int t = 0; t < SEQ; t++) {
        float* shrow = sh[t & 1];
        if (warp == 0) {
            if (lane < 16) {
                const int tgt = (t + 1) * 64;
                while (ldacq(a.hctr + lane * CSTRIDE) < tgt) { }
            }
            __syncwarp();
            const float* hrow = a.Hin + t * HID;
#pragma unroll
            for (int i = 0; i < 8; i++)
                *(float4*)(shrow + i * 128 + lane * 4) = ldcg4(hrow + i * 128 + lane * 4);
        }
        __syncthreads();

        for (int o = o0 + warp; o < o1; o += 8) {
            const float* wrow = (o < 1024) ? a.Wa + o * HID : a.Wb + (o - 1024) * HID;
            float* dst = (o < 1024) ? a.Zu + t * HID + o : a.Zr + t * HID + (o - 1024);
            ull acc = 0;
#pragma unroll
            for (int i = 0; i < 8; i++) {
                float4 w4 = __ldg((const float4*)(wrow + i * 128 + lane * 4));
                float4 h4 = *(const float4*)(shrow + i * 128 + lane * 4);
                acc = fma2(pack2(w4.x, w4.y), pack2(h4.x, h4.y), acc);
                acc = fma2(pack2(w4.z, w4.w), pack2(h4.z, h4.w), acc);
            }
            float s = sum2(acc);
#pragma unroll
            for (int off = 16; off > 0; off >>= 1)
                s += __shfl_xor_sync(0xffffffffu, s, off);
            if (lane == 0) stcg(dst, s);
        }
        if (lane == 0) red_release_add(myctr, 1);   // per-warp release (8/CTA/step)
    }
}

__global__ __launch_bounds__(256, 2) void mega_kernel(MegaArgs A) {
    __shared__ float sh[2][HID];
    const int b = blockIdx.x;
    // bid layout: s0[0,128) g0[128,148) s1[148,276) g1[276,296)
    //             s2[296,424) g2[424,444) s3[444,572)
    if (b < 128)      scan_body(A.s[0], b, sh);
    else if (b < 148) g_body(A.g[0], b - 128, sh);
    else if (b < 276) scan_body(A.s[1], b - 148, sh);
    else if (b < 296) g_body(A.g[1], b - 276, sh);
    else if (b < 424) scan_body(A.s[2], b - 296, sh);
    else if (b < 444) g_body(A.g[2], b - 424, sh);
    else              scan_body(A.s[3], b - 444, sh);
}

// ---------------- launch ----------------
extern "C" void kernel_launch(void* const* d_in, const int* in_sizes, int n_in,
                              void* d_out, int out_size) {
    const float* x   = (const float*)d_in[0];
    const float* Uu  = (const float*)d_in[1];
    const float* Ur  = (const float*)d_in[2];
    const float* U   = (const float*)d_in[3];
    const float* Wu  = (const float*)d_in[4];
    const float* Wr  = (const float*)d_in[5];
    const float* W   = (const float*)d_in[6];
    const float* Bu  = (const float*)d_in[7];
    const float* Br  = (const float*)d_in[8];
    const float* B   = (const float*)d_in[9];
    const float* Uhr = (const float*)d_in[10];
    const float* Uh  = (const float*)d_in[11];
    float* out = (float*)d_out;

    float *Z0u, *Z0r, *Z0c, *Zu, *Zr, *Hb;
    int *hc, *gc;
    cudaGetSymbolAddress((void**)&Z0u, g_Z0u);
    cudaGetSymbolAddress((void**)&Z0r, g_Z0r);
    cudaGetSymbolAddress((void**)&Z0c, g_Z0c);
    cudaGetSymbolAddress((void**)&Zu,  g_Zu);
    cudaGetSymbolAddress((void**)&Zr,  g_Zr);
    cudaGetSymbolAddress((void**)&Hb,  g_H);
    cudaGetSymbolAddress((void**)&hc,  g_hctr);
    cudaGetSymbolAddress((void**)&gc,  g_gctr);

    reset_ctrs_kernel<<<(NLAYERS * 16 * CSTRIDE + 255) / 256, 256>>>();

    {   // layer 0 input projections
        dim3 gg(HID / 128, SEQ / 128, 3);
        GemmJob a{x, Uu, Z0u}, b{x, Ur, Z0r}, c{x, U, Z0c};
        sgemm_nt_batch<<<gg, 256>>>(a, b, c);
    }

    MegaArgs A;
    for (int l = 0; l < NLAYERS; l++) {
        ScanArgs& s = A.s[l];
        s.Wu = Wu + (size_t)l * HID * HID;
        s.Wr = Wr + (size_t)l * HID * HID;
        s.Wc = W  + (size_t)l * HID * HID;
        s.Bu = Bu + l * HID; s.Br = Br + l * HID; s.Bc = B + l * HID;
        if (l == 0) { s.Pu = Z0u; s.Pr = Z0r; s.Pc = Z0c; s.gctr = nullptr; }
        else {
            s.Pu = Zu + (size_t)(l - 1) * SEQ * HID;
            s.Pr = Zr + (size_t)(l - 1) * SEQ * HID;
            s.Pc = s.Pu;                        // shared term feeds u AND c
            s.gctr = gc + (l - 1) * GCTA * CSTRIDE;
        }
        s.H = Hb + (size_t)l * SEQ * HID;
        s.outf = out + l * HID;
        s.hctr = hc + l * 16 * CSTRIDE;
    }
    for (int l = 0; l < 3; l++) {
        GArgs& g = A.g[l];
        g.Wa = Uh  + (size_t)l * HID * HID;     // shared (update + candidate)
        g.Wb = Uhr + (size_t)l * HID * HID;     // reset gate
        g.Hin = Hb + (size_t)l * SEQ * HID;
        g.Zu = Zu + (size_t)l * SEQ * HID;
        g.Zr = Zr + (size_t)l * SEQ * HID;
        g.hctr = hc + l * 16 * CSTRIDE;
        g.gctr = gc + l * GCTA * CSTRIDE;
    }
    mega_kernel<<<572, 256>>>(A);
    (void)in_sizes; (void)n_in; (void)out_size;
}

// round 9
// speedup vs baseline: 1.9633x; 1.9633x over previous
#include <cuda_runtime.h>

#define SEQ 4096
#define HID 1024
#define NLAYERS 4
#define NCTA 128
#define CSTRIDE 32
#define NSLOT 16

// ---------------- device scratch ----------------
__device__ float g_Zu[SEQ * HID];          // layer A input terms (u)
__device__ float g_Zr[SEQ * HID];          // (r)
__device__ float g_Zc[SEQ * HID];          // (c) — distinct only for layer 0
__device__ float g_H[NLAYERS][SEQ * HID];
__device__ int   g_ctr[2][2][NSLOT * CSTRIDE];   // [pair][A/B][slot]

__global__ void reset_ctrs_kernel() {
    int i = blockIdx.x * blockDim.x + threadIdx.x;
    if (i < 2 * 2 * NSLOT * CSTRIDE) ((int*)g_ctr)[i] = 0;
}

// ---------------- memory helpers ----------------
__device__ __forceinline__ float4 ldcg4(const float* p) {
    float4 v;
    asm volatile("ld.global.cg.v4.f32 {%0,%1,%2,%3},[%4];"
                 : "=f"(v.x), "=f"(v.y), "=f"(v.z), "=f"(v.w) : "l"(p) : "memory");
    return v;
}
__device__ __forceinline__ void stcg(float* p, float v) {
    asm volatile("st.global.cg.f32 [%0],%1;" :: "l"(p), "f"(v) : "memory");
}
__device__ __forceinline__ int ldacq(const int* p) {
    int v;
    asm volatile("ld.acquire.gpu.global.s32 %0,[%1];" : "=r"(v) : "l"(p) : "memory");
    return v;
}
__device__ __forceinline__ void red_release_add(int* p, int v) {
    asm volatile("red.release.gpu.global.add.s32 [%0],%1;" :: "l"(p), "r"(v) : "memory");
}

typedef unsigned long long ull;
__device__ __forceinline__ ull pack2(float lo, float hi) {
    ull r; asm("mov.b64 %0,{%1,%2};" : "=l"(r) : "f"(lo), "f"(hi)); return r;
}
__device__ __forceinline__ ull fma2(ull a, ull b, ull c) {
    ull d; asm("fma.rn.f32x2 %0,%1,%2,%3;" : "=l"(d) : "l"(a), "l"(b), "l"(c)); return d;
}
__device__ __forceinline__ float sum2(ull v) {
    float lo, hi; asm("mov.b64 {%0,%1},%2;" : "=f"(lo), "=f"(hi) : "l"(v));
    return lo + hi;
}
__device__ __forceinline__ float sigmoidf_(float x) {
    return 1.f / (1.f + __expf(-x));
}

// ---------------- fp32 SGEMM batch: C[z] = A[z] @ B[z]^T ----------------
struct GemmJob { const float* A; const float* B; float* C; };
__global__ __launch_bounds__(256) void sgemm_nt_batch(GemmJob j0, GemmJob j1, GemmJob j2) {
    const GemmJob job = (blockIdx.z == 0) ? j0 : (blockIdx.z == 1) ? j1 : j2;
    const float* __restrict__ A = job.A;
    const float* __restrict__ B = job.B;
    float* __restrict__ C = job.C;
    const int K = HID, N = HID;
    __shared__ float As[8][128];
    __shared__ float Bs[8][128];
    const int tid = threadIdx.x;
    const int m0 = blockIdx.y * 128;
    const int n0 = blockIdx.x * 128;
    const int tx = tid & 15;
    const int ty = tid >> 4;
    const int lrow = tid >> 1;
    const int kp = (tid & 1) * 4;

    const float* Ap = A + (m0 + lrow) * K + kp;
    const float* Bp = B + (n0 + lrow) * K + kp;

    float acc[8][8];
#pragma unroll
    for (int i = 0; i < 8; i++)
#pragma unroll
        for (int j = 0; j < 8; j++) acc[i][j] = 0.f;

    for (int k0 = 0; k0 < K; k0 += 8) {
        float4 av = *(const float4*)(Ap + k0);
        float4 bv = *(const float4*)(Bp + k0);
        __syncthreads();
        As[kp + 0][lrow] = av.x; As[kp + 1][lrow] = av.y;
        As[kp + 2][lrow] = av.z; As[kp + 3][lrow] = av.w;
        Bs[kp + 0][lrow] = bv.x; Bs[kp + 1][lrow] = bv.y;
        Bs[kp + 2][lrow] = bv.z; Bs[kp + 3][lrow] = bv.w;
        __syncthreads();
#pragma unroll
        for (int kk = 0; kk < 8; kk++) {
            float a[8], b[8];
#pragma unroll
            for (int i = 0; i < 8; i++) a[i] = As[kk][ty * 8 + i];
#pragma unroll
            for (int j = 0; j < 8; j++) b[j] = Bs[kk][tx * 8 + j];
#pragma unroll
            for (int i = 0; i < 8; i++)
#pragma unroll
                for (int j = 0; j < 8; j++) acc[i][j] = fmaf(a[i], b[j], acc[i][j]);
        }
    }
#pragma unroll
    for (int i = 0; i < 8; i++) {
        float* Cp = C + (m0 + ty * 8 + i) * N + n0 + tx * 8;
#pragma unroll
        for (int j = 0; j < 8; j++) Cp[j] = acc[i][j];
    }
}

// ---------------- fused 2-layer GRU scan ----------------
// 128 CTAs x 512 threads. Warps 0-7: layer A output j=8b+w (3 reg rows).
// Warps 8-15: layer B output j=8b+(w-8): Wu,Wr in regs; Wc,Uh,Uhr in SMEM.
// Round R: warp0 stages hA(R-1) (serves A's h and B's input), warp1 stages
// hB(R-2). A computes hA(R) (R<SEQ); B computes hB(R-1) (R>=1). 4097 rounds.
struct PairArgs {
    // layer A
    const float *WuA, *WrA, *WcA, *BuA, *BrA, *BcA, *Pu, *Pr, *Pc;
    float *HA, *outA;
    // layer B
    const float *WuB, *WrB, *WcB, *BuB, *BrB, *BcB, *Uh, *Uhr;
    float *HB, *outB;
    int *ctrA, *ctrB;
};

__global__ __launch_bounds__(512, 1) void pair_scan(PairArgs a) {
    extern __shared__ float smem[];
    float* uhw  = smem;                 // [8][1024] Uh rows
    float* uhrw = smem + 8 * HID;       // [8][1024] Uhr rows
    float* wcbw = smem + 16 * HID;      // [8][1024] Wc(B) rows
    float* shA  = smem + 24 * HID;      // [2][1024] staged hA
    float* shB  = smem + 26 * HID;      // [2][1024] staged hB

    const int tid = threadIdx.x;
    const int warp = tid >> 5;
    const int lane = tid & 31;
    const int isB = warp >> 3;
    const int w8 = warp & 7;
    const int j = (blockIdx.x << 3) + w8;
    const int slot = (blockIdx.x & (NSLOT - 1)) * CSTRIDE;

    // cooperative SMEM weight load (rows for this CTA's 8 B-outputs)
    for (int idx = tid; idx < 8 * HID; idx += 512) {
        const int row = idx >> 10, col = idx & (HID - 1);
        const int gj = (blockIdx.x << 3) + row;
        uhw[idx]  = a.Uh[(size_t)gj * HID + col];
        uhrw[idx] = a.Uhr[(size_t)gj * HID + col];
        wcbw[idx] = a.WcB[(size_t)gj * HID + col];
    }

    // register weight rows
    ull wu2[16], wr2[16], wc2[16];
    {
        const float* wub = (isB ? a.WuB : a.WuA) + (size_t)j * HID;
        const float* wrb = (isB ? a.WrB : a.WrA) + (size_t)j * HID;
#pragma unroll
        for (int i = 0; i < 8; i++) {
            const int k = i * 128 + lane * 4;
            float4 x = *(const float4*)(wub + k);
            float4 y = *(const float4*)(wrb + k);
            wu2[2 * i] = pack2(x.x, x.y); wu2[2 * i + 1] = pack2(x.z, x.w);
            wr2[2 * i] = pack2(y.x, y.y); wr2[2 * i + 1] = pack2(y.z, y.w);
        }
        if (!isB) {
            const float* wcb = a.WcA + (size_t)j * HID;
#pragma unroll
            for (int i = 0; i < 8; i++) {
                const int k = i * 128 + lane * 4;
                float4 z = *(const float4*)(wcb + k);
                wc2[2 * i] = pack2(z.x, z.y); wc2[2 * i + 1] = pack2(z.z, z.w);
            }
        }
    }
    const float bu = isB ? a.BuB[j] : a.BuA[j];
    const float br = isB ? a.BrB[j] : a.BrA[j];
    const float bc = isB ? a.BcB[j] : a.BcA[j];
    float hj = 0.f;
    __syncthreads();   // SMEM weights ready

    for (int R = 0; R <= SEQ; R++) {
        float* sA = shA + (R & 1) * HID;
        float* sB = shB + (R & 1) * HID;
        if (warp == 0) {
            if (R > 0) {
                if (lane < NSLOT) {
                    const int tgt = R * 64;
                    while (ldacq(a.ctrA + lane * CSTRIDE) < tgt) { }
                }
                __syncwarp();
                const float* hrow = a.HA + (size_t)(R - 1) * HID;
#pragma unroll
                for (int i = 0; i < 8; i++)
                    *(float4*)(sA + i * 128 + lane * 4) = ldcg4(hrow + i * 128 + lane * 4);
            } else {
#pragma unroll
                for (int i = 0; i < 8; i++)
                    *(float4*)(sA + i * 128 + lane * 4) = make_float4(0.f, 0.f, 0.f, 0.f);
            }
        } else if (warp == 1) {
            if (R >= 2) {
                if (lane < NSLOT) {
                    const int tgt = (R - 1) * 64;
                    while (ldacq(a.ctrB + lane * CSTRIDE) < tgt) { }
                }
                __syncwarp();
                const float* hrow = a.HB + (size_t)(R - 2) * HID;
#pragma unroll
                for (int i = 0; i < 8; i++)
                    *(float4*)(sB + i * 128 + lane * 4) = ldcg4(hrow + i * 128 + lane * 4);
            } else {
#pragma unroll
                for (int i = 0; i < 8; i++)
                    *(float4*)(sB + i * 128 + lane * 4) = make_float4(0.f, 0.f, 0.f, 0.f);
            }
        }
        __syncthreads();   // single barrier per round

        if (!isB) {
            if (R < SEQ) {
                const int t = R;
                const float zu = __ldg(a.Pu + (size_t)t * HID + j);
                const float zr = __ldg(a.Pr + (size_t)t * HID + j);
                const float zc = __ldg(a.Pc + (size_t)t * HID + j);
                ull au2 = 0, ar2 = 0, ac2 = 0;
#pragma unroll
                for (int i = 0; i < 8; i++) {
                    float4 h4 = *(const float4*)(sA + i * 128 + lane * 4);
                    const ull h01 = pack2(h4.x, h4.y);
                    const ull h23 = pack2(h4.z, h4.w);
                    au2 = fma2(wu2[2 * i], h01, au2);
                    ar2 = fma2(wr2[2 * i], h01, ar2);
                    ac2 = fma2(wc2[2 * i], h01, ac2);
                    au2 = fma2(wu2[2 * i + 1], h23, au2);
                    ar2 = fma2(wr2[2 * i + 1], h23, ar2);
                    ac2 = fma2(wc2[2 * i + 1], h23, ac2);
                }
                float au = sum2(au2), ar = sum2(ar2), ac = sum2(ac2);
#pragma unroll
                for (int off = 16; off > 0; off >>= 1) {
                    au += __shfl_xor_sync(0xffffffffu, au, off);
                    ar += __shfl_xor_sync(0xffffffffu, ar, off);
                    ac += __shfl_xor_sync(0xffffffffu, ac, off);
                }
                const float u = sigmoidf_(au + zu + bu);
                const float r = sigmoidf_(ar + zr + br);
                const float c = sigmoidf_(zc + r * ac + bc);
                hj = fmaf(u, hj - c, c);
                if (lane == 0) {
                    stcg(a.HA + (size_t)t * HID + j, hj);
                    red_release_add(a.ctrA + slot, 1);
                }
            }
        } else {
            if (R >= 1) {
                const int t = R - 1;
                const float* uhp  = uhw  + w8 * HID;
                const float* uhrp = uhrw + w8 * HID;
                const float* wcp  = wcbw + w8 * HID;
                ull au2 = 0, ar2 = 0, ac2 = 0, as2 = 0, aq2 = 0;
#pragma unroll
                for (int i = 0; i < 8; i++) {
                    const int k = i * 128 + lane * 4;
                    float4 hB4 = *(const float4*)(sB + k);
                    float4 hA4 = *(const float4*)(sA + k);
                    float4 wc4 = *(const float4*)(wcp + k);
                    float4 uh4 = *(const float4*)(uhp + k);
                    float4 uq4 = *(const float4*)(uhrp + k);
                    const ull b01 = pack2(hB4.x, hB4.y), b23 = pack2(hB4.z, hB4.w);
                    const ull a01 = pack2(hA4.x, hA4.y), a23 = pack2(hA4.z, hA4.w);
                    au2 = fma2(wu2[2 * i], b01, au2);
                    ar2 = fma2(wr2[2 * i], b01, ar2);
                    ac2 = fma2(pack2(wc4.x, wc4.y), b01, ac2);
                    as2 = fma2(pack2(uh4.x, uh4.y), a01, as2);
                    aq2 = fma2(pack2(uq4.x, uq4.y), a01, aq2);
                    au2 = fma2(wu2[2 * i + 1], b23, au2);
                    ar2 = fma2(wr2[2 * i + 1], b23, ar2);
                    ac2 = fma2(pack2(wc4.z, wc4.w), b23, ac2);
                    as2 = fma2(pack2(uh4.z, uh4.w), a23, as2);
                    aq2 = fma2(pack2(uq4.z, uq4.w), a23, aq2);
                }
                float au = sum2(au2), ar = sum2(ar2), ac = sum2(ac2);
                float as = sum2(as2), aq = sum2(aq2);
#pragma unroll
                for (int off = 16; off > 0; off >>= 1) {
                    au += __shfl_xor_sync(0xffffffffu, au, off);
                    ar += __shfl_xor_sync(0xffffffffu, ar, off);
                    ac += __shfl_xor_sync(0xffffffffu, ac, off);
                    as += __shfl_xor_sync(0xffffffffu, as, off);
                    aq += __shfl_xor_sync(0xffffffffu, aq, off);
                }
                // shared term 'as' feeds BOTH u and c (aliased Uh); 'aq' feeds r
                const float u = sigmoidf_(as + au + bu);
                const float r = sigmoidf_(aq + ar + br);
                const float c = sigmoidf_(as + r * ac + bc);
                hj = fmaf(u, hj - c, c);
                if (lane == 0) {
                    stcg(a.HB + (size_t)t * HID + j, hj);
                    red_release_add(a.ctrB + slot, 1);
                }
            }
        }
    }
    if (lane == 0) {
        if (!isB) a.outA[j] = hj;
        else      a.outB[j] = hj;
    }
}

// ---------------- launch ----------------
extern "C" void kernel_launch(void* const* d_in, const int* in_sizes, int n_in,
                              void* d_out, int out_size) {
    const float* x   = (const float*)d_in[0];
    const float* Uu  = (const float*)d_in[1];
    const float* Ur  = (const float*)d_in[2];
    const float* U   = (const float*)d_in[3];
    const float* Wu  = (const float*)d_in[4];
    const float* Wr  = (const float*)d_in[5];
    const float* W   = (const float*)d_in[6];
    const float* Bu  = (const float*)d_in[7];
    const float* Br  = (const float*)d_in[8];
    const float* B   = (const float*)d_in[9];
    const float* Uhr = (const float*)d_in[10];
    const float* Uh  = (const float*)d_in[11];
    float* out = (float*)d_out;

    float *Zu, *Zr, *Zc, *Hb;
    int* ct;
    cudaGetSymbolAddress((void**)&Zu, g_Zu);
    cudaGetSymbolAddress((void**)&Zr, g_Zr);
    cudaGetSymbolAddress((void**)&Zc, g_Zc);
    cudaGetSymbolAddress((void**)&Hb, g_H);
    cudaGetSymbolAddress((void**)&ct, g_ctr);

    const int smem_bytes = 28 * HID * sizeof(float);   // 112 KB
    cudaFuncSetAttribute(pair_scan, cudaFuncAttributeMaxDynamicSharedMemorySize, smem_bytes);

    reset_ctrs_kernel<<<(2 * 2 * NSLOT * CSTRIDE + 255) / 256, 256>>>();

    {   // layer 0 input projections
        dim3 gg(HID / 128, SEQ / 128, 3);
        GemmJob A0{x, Uu, Zu}, B0{x, Ur, Zr}, C0{x, U, Zc};
        sgemm_nt_batch<<<gg, 256>>>(A0, B0, C0);
    }

    const size_t HH = (size_t)HID * HID;
    float* H0 = Hb;
    float* H1 = Hb + (size_t)SEQ * HID;
    float* H2 = Hb + 2 * (size_t)SEQ * HID;
    float* H3 = Hb + 3 * (size_t)SEQ * HID;

    // pair 0: layers 0 (A) + 1 (B)
    {
        PairArgs p;
        p.WuA = Wu; p.WrA = Wr; p.WcA = W;
        p.BuA = Bu; p.BrA = Br; p.BcA = B;
        p.Pu = Zu; p.Pr = Zr; p.Pc = Zc;
        p.HA = H0; p.outA = out;
        p.WuB = Wu + HH; p.WrB = Wr + HH; p.WcB = W + HH;
        p.BuB = Bu + HID; p.BrB = Br + HID; p.BcB = B + HID;
        p.Uh = Uh; p.Uhr = Uhr;
        p.HB = H1; p.outB = out + HID;
        p.ctrA = ct; p.ctrB = ct + NSLOT * CSTRIDE;
        pair_scan<<<NCTA, 512, smem_bytes>>>(p);
    }

    {   // layer 2 input terms from H1: shared = Uh[1]@H1, reset = Uhr[1]@H1
        dim3 gg(HID / 128, SEQ / 128, 2);
        GemmJob A1{H1, Uh + HH, Zu}, B1{H1, Uhr + HH, Zr};
        sgemm_nt_batch<<<gg, 256>>>(A1, B1, A1);
    }

    // pair 1: layers 2 (A) + 3 (B)
    {
        PairArgs p;
        p.WuA = Wu + 2 * HH; p.WrA = Wr + 2 * HH; p.WcA = W + 2 * HH;
        p.BuA = Bu + 2 * HID; p.BrA = Br + 2 * HID; p.BcA = B + 2 * HID;
        p.Pu = Zu; p.Pr = Zr; p.Pc = Zu;            // shared term aliases u & c
        p.HA = H2; p.outA = out + 2 * HID;
        p.WuB = Wu + 3 * HH; p.WrB = Wr + 3 * HH; p.WcB = W + 3 * HH;
        p.BuB = Bu + 3 * HID; p.BrB = Br + 3 * HID; p.BcB = B + 3 * HID;
        p.Uh = Uh + 2 * HH; p.Uhr = Uhr + 2 * HH;
        p.HB = H3; p.outB = out + 3 * HID;
        p.ctrA = ct + 2 * NSLOT * CSTRIDE; p.ctrB = ct + 3 * NSLOT * CSTRIDE;
        pair_scan<<<NCTA, 512, smem_bytes>>>(p);
    }
    (void)in_sizes; (void)n_in; (void)out_size;
}

// round 11
// speedup vs baseline: 2.1060x; 1.0727x over previous
#include <cuda_runtime.h>
#include <cuda_fp16.h>

#define SEQ 4096
#define HID 1024
#define NCTA 128
#define CSTRIDE 32
#define NSLOT 16
#define NCH 9            // chains per warp; 16 warps x 9 = 144 chains

// ---------------- device scratch ----------------
__device__ float g_Zu[SEQ * HID];
__device__ float g_Zr[SEQ * HID];
__device__ float g_Zc[SEQ * HID];
__device__ float g_H[4][SEQ * HID];
__device__ int   g_ctr[4][NSLOT * CSTRIDE];

__global__ void reset_ctrs_kernel() {
    int i = blockIdx.x * blockDim.x + threadIdx.x;
    if (i < 4 * NSLOT * CSTRIDE) ((int*)g_ctr)[i] = 0;
}

// ---------------- memory helpers (proven R7 sync primitives) ----------------
__device__ __forceinline__ float4 ldcg4(const float* p) {
    float4 v;
    asm volatile("ld.global.cg.v4.f32 {%0,%1,%2,%3},[%4];"
                 : "=f"(v.x), "=f"(v.y), "=f"(v.z), "=f"(v.w) : "l"(p) : "memory");
    return v;
}
__device__ __forceinline__ void stcg(float* p, float v) {
    asm volatile("st.global.cg.f32 [%0],%1;" :: "l"(p), "f"(v) : "memory");
}
__device__ __forceinline__ int ldacq(const int* p) {
    int v;
    asm volatile("ld.acquire.gpu.global.s32 %0,[%1];" : "=r"(v) : "l"(p) : "memory");
    return v;
}
__device__ __forceinline__ void red_release_add(int* p, int v) {
    asm volatile("red.release.gpu.global.add.s32 [%0],%1;" :: "l"(p), "r"(v) : "memory");
}
__device__ __forceinline__ float sigf(float x) { return 1.f / (1.f + __expf(-x)); }

// pack two floats to one half2 stored as uint (trivially copyable carriers)
__device__ __forceinline__ unsigned pack_h2(float a, float b) {
    __half2 h = __floats2half2_rn(a, b);
    return *(unsigned*)&h;
}

// fp16 SIMD dot of 8 elems (two uint4 = 4 half2 each), fp32 result.
__device__ __forceinline__ float dot4u(const uint4& wv, const uint4& hv) {
    const __half2* w = (const __half2*)&wv;
    const __half2* h = (const __half2*)&hv;
    __half2 acc = __hmul2(w[0], h[0]);
    acc = __hfma2(w[1], h[1], acc);
    acc = __hfma2(w[2], h[2], acc);
    acc = __hfma2(w[3], h[3], acc);
    float2 f = __half22float2(acc);
    return f.x + f.y;
}

// ---------------- fp32 SGEMM batch (layer-0 input projections) -------------
struct GemmJob { const float* A; const float* B; float* C; };
__global__ __launch_bounds__(256) void sgemm_nt_batch(GemmJob j0, GemmJob j1, GemmJob j2) {
    const GemmJob job = (blockIdx.z == 0) ? j0 : (blockIdx.z == 1) ? j1 : j2;
    const float* __restrict__ A = job.A;
    const float* __restrict__ B = job.B;
    float* __restrict__ C = job.C;
    const int K = HID, N = HID;
    __shared__ float As[8][128];
    __shared__ float Bs[8][128];
    const int tid = threadIdx.x;
    const int m0 = blockIdx.y * 128;
    const int n0 = blockIdx.x * 128;
    const int tx = tid & 15;
    const int ty = tid >> 4;
    const int lrow = tid >> 1;
    const int kp = (tid & 1) * 4;

    const float* Ap = A + (m0 + lrow) * K + kp;
    const float* Bp = B + (n0 + lrow) * K + kp;

    float acc[8][8];
#pragma unroll
    for (int i = 0; i < 8; i++)
#pragma unroll
        for (int j = 0; j < 8; j++) acc[i][j] = 0.f;

    for (int k0 = 0; k0 < K; k0 += 8) {
        float4 av = *(const float4*)(Ap + k0);
        float4 bv = *(const float4*)(Bp + k0);
        __syncthreads();
        As[kp + 0][lrow] = av.x; As[kp + 1][lrow] = av.y;
        As[kp + 2][lrow] = av.z; As[kp + 3][lrow] = av.w;
        Bs[kp + 0][lrow] = bv.x; Bs[kp + 1][lrow] = bv.y;
        Bs[kp + 2][lrow] = bv.z; Bs[kp + 3][lrow] = bv.w;
        __syncthreads();
#pragma unroll
        for (int kk = 0; kk < 8; kk++) {
            float a[8], b[8];
#pragma unroll
            for (int i = 0; i < 8; i++) a[i] = As[kk][ty * 8 + i];
#pragma unroll
            for (int j = 0; j < 8; j++) b[j] = Bs[kk][tx * 8 + j];
#pragma unroll
            for (int i = 0; i < 8; i++)
#pragma unroll
                for (int j = 0; j < 8; j++) acc[i][j] = fmaf(a[i], b[j], acc[i][j]);
        }
    }
#pragma unroll
    for (int i = 0; i < 8; i++) {
        float* Cp = C + (m0 + ty * 8 + i) * N + n0 + tx * 8;
#pragma unroll
        for (int j = 0; j < 8; j++) Cp[j] = acc[i][j];
    }
}

// ---------------- quad-layer fused GRU scan ----------------
// 128 CTAs x 512 threads (16 warps). Chain c (0..143) ordered by input vector
// v: [0,40) h0 = L0 rec(24)+L1 s,q(16); [40,80) h1; [80,120) h2; [120,144) h3
// = L3 rec. Warp w owns chains [9w, 9w+9): first 3 in regs (uint4 x4), 6 in
// SMEM fp16. Round R: layer l computes t=R-l. Warps 0-3 poll+stage
// h_l(R-1-l) into fp16 SMEM; barA; chains + shfl reduce -> res[]; barB;
// warp 15 lane i = instance (l=i>>3, j=i&7) does gates + st.cg + release.
struct QuadArgs {
    const float *Wu, *Wr, *Wc, *Bu, *Br, *Bc, *Uh, *Uhr, *Zu, *Zr, *Zc;
    float *H, *out;
    int *ctr;
};

#define WROW_BYTES (96 * 2048)
#define HBUF_BYTES (4 * 2048)
#define SMEM_TOTAL_Q (WROW_BYTES + HBUF_BYTES + 160 * 4)

__global__ __launch_bounds__(512, 1) void quad_scan(QuadArgs a) {
    extern __shared__ char smem[];
    char* wrow_b = smem;
    char* hbuf_b = smem + WROW_BYTES;
    float* res   = (float*)(smem + WROW_BYTES + HBUF_BYTES);

    const int tid = threadIdx.x;
    const int w = tid >> 5, L = tid & 31;
    const int bid = blockIdx.x;
    const size_t HH = (size_t)HID * HID;

    // majority input vector for this warp = vector of middle chain
    const int c4 = w * NCH + 4;
    const int vMaj = (c4 < 40) ? 0 : (c4 < 80) ? 1 : (c4 < 120) ? 2 : 3;

    uint4 wreg[3][4];
    int meta[NCH];

    // ---- init: resolve chains, convert weights to fp16 (regs / SMEM) ----
#pragma unroll
    for (int k = 0; k < NCH; k++) {
        const int c = w * NCH + k;
        const int v = (c < 40) ? 0 : (c < 80) ? 1 : (c < 120) ? 2 : 3;
        const int g = c - 40 * v;
        int l, j, kind;
        if (v == 3 || g < 24) { l = v; j = g / 3; kind = g - 3 * j; }
        else { const int gg = g - 24; l = v + 1; j = gg >> 1; kind = 3 + (gg & 1); }
        const int jf = (bid << 3) + j;
        const float* wp;
        if (kind == 0)      wp = a.Wu  + (size_t)l * HH + (size_t)jf * HID;
        else if (kind == 1) wp = a.Wr  + (size_t)l * HH + (size_t)jf * HID;
        else if (kind == 2) wp = a.Wc  + (size_t)l * HH + (size_t)jf * HID;
        else if (kind == 3) wp = a.Uh  + (size_t)(l - 1) * HH + (size_t)jf * HID;
        else                wp = a.Uhr + (size_t)(l - 1) * HH + (size_t)jf * HID;
        const int roff = (l * 8 + j) * 5 + kind;
        meta[k] = l | (((v == vMaj) ? 1 : 0) << 2) | (v << 3) | (roff << 5);

        unsigned tmp[16];
        const float* rp = wp + 32 * L;
#pragma unroll
        for (int i = 0; i < 8; i++) {
            float4 f = __ldg((const float4*)rp + i);
            tmp[2 * i]     = pack_h2(f.x, f.y);
            tmp[2 * i + 1] = pack_h2(f.z, f.w);
        }
        if (k < 3) {
#pragma unroll
            for (int q = 0; q < 4; q++)
                wreg[k][q] = make_uint4(tmp[4 * q], tmp[4 * q + 1],
                                        tmp[4 * q + 2], tmp[4 * q + 3]);
        } else {
            char* rb = wrow_b + (size_t)(w * 6 + (k - 3)) * 2048;
#pragma unroll
            for (int q = 0; q < 4; q++)
                *(uint4*)(rb + q * 512 + L * 16) =
                    make_uint4(tmp[4 * q], tmp[4 * q + 1],
                               tmp[4 * q + 2], tmp[4 * q + 3]);
        }
    }

    // gate-lane state (warp 15, lane = instance)
    float hj = 0.f, bu = 0.f, br = 0.f, bc = 0.f;
    int gl = 0, gj = 0;
    if (w == 15) {
        gl = L >> 3; gj = (bid << 3) + (L & 7);
        bu = a.Bu[gl * HID + gj]; br = a.Br[gl * HID + gj]; bc = a.Bc[gl * HID + gj];
    }
    __syncthreads();

    for (int R = 0; R < SEQ + 3; R++) {
        // prefetch layer-0 gate input terms (hidden under staging)
        float zu = 0.f, zr = 0.f, zc = 0.f;
        if (w == 15 && gl == 0 && R < SEQ) {
            zu = __ldg(a.Zu + (size_t)R * HID + gj);
            zr = __ldg(a.Zr + (size_t)R * HID + gj);
            zc = __ldg(a.Zc + (size_t)R * HID + gj);
        }
        // stage: warp l brings h_l(R-1-l) into fp16 SMEM
        if (w < 4) {
            const int l = w;
            char* hb = hbuf_b + l * 2048;
            if (R >= l + 1) {
                int row = R - 1 - l; if (row > SEQ - 1) row = SEQ - 1;
                int tgt = R - l;     if (tgt > SEQ) tgt = SEQ;
                tgt *= 64;
                if (L < NSLOT) {
                    const int* cp = a.ctr + l * (NSLOT * CSTRIDE) + L * CSTRIDE;
                    while (ldacq(cp) < tgt) { }
                }
                __syncwarp();
                const float* hr = a.H + ((size_t)l * SEQ + row) * HID + 32 * L;
                unsigned hv[16];
#pragma unroll
                for (int i = 0; i < 8; i++) {
                    float4 f = ldcg4(hr + 4 * i);
                    hv[2 * i]     = pack_h2(f.x, f.y);
                    hv[2 * i + 1] = pack_h2(f.z, f.w);
                }
#pragma unroll
                for (int q = 0; q < 4; q++)
                    *(uint4*)(hb + L * 64 + q * 16) =
                        make_uint4(hv[4 * q], hv[4 * q + 1],
                                   hv[4 * q + 2], hv[4 * q + 3]);
            } else {
                const uint4 z = make_uint4(0, 0, 0, 0);
#pragma unroll
                for (int q = 0; q < 4; q++) *(uint4*)(hb + L * 64 + q * 16) = z;
            }
        }
        __syncthreads();   // bar A: all 4 staged vectors ready

        // cache majority vector in regs
        uint4 hc[4];
#pragma unroll
        for (int q = 0; q < 4; q++)
            hc[q] = *(const uint4*)(hbuf_b + vMaj * 2048 + L * 64 + q * 16);

        // chains
#pragma unroll
        for (int k = 0; k < NCH; k++) {
            const int m = meta[k];
            const int l = m & 3;
            const int t = R - l;
            if (t < 0 || t >= SEQ) continue;
            const bool cached = (m >> 2) & 1;
            const int v = (m >> 3) & 3;
            float s = 0.f;
#pragma unroll
            for (int q = 0; q < 4; q++) {
                uint4 hg;
                if (cached) hg = hc[q];
                else hg = *(const uint4*)(hbuf_b + v * 2048 + L * 64 + q * 16);
                uint4 wg;
                if (k < 3) wg = wreg[k][q];
                else wg = *(const uint4*)(wrow_b + (size_t)(w * 6 + (k - 3)) * 2048 + q * 512 + L * 16);
                s += dot4u(wg, hg);
            }
#pragma unroll
            for (int off = 16; off > 0; off >>= 1)
                s += __shfl_xor_sync(0xffffffffu, s, off);
            if (L == 0) res[m >> 5] = s;
        }
        __syncthreads();   // bar B: res[] complete

        // gates: warp 15, lane = instance (l = L>>3, j = L&7)
        if (w == 15) {
            const int t = R - gl;
            if (t >= 0 && t < SEQ) {
                const float r0 = res[L * 5 + 0], r1 = res[L * 5 + 1], r2 = res[L * 5 + 2];
                float u, r, c;
                if (gl == 0) {
                    u = sigf(r0 + zu + bu);
                    r = sigf(r1 + zr + br);
                    c = sigf(zc + r * r2 + bc);
                } else {
                    const float s5 = res[L * 5 + 3], q5 = res[L * 5 + 4];
                    u = sigf(s5 + r0 + bu);       // shared Uh term feeds u...
                    r = sigf(q5 + r1 + br);
                    c = sigf(s5 + r * r2 + bc);   // ...and c (aliased parameter)
                }
                hj = fmaf(u, hj - c, c);
                stcg(a.H + ((size_t)gl * SEQ + t) * HID + gj, hj);
                red_release_add(a.ctr + gl * (NSLOT * CSTRIDE) + (bid & (NSLOT - 1)) * CSTRIDE, 1);
                if (t == SEQ - 1) a.out[gl * HID + gj] = hj;
            }
        }
    }
}

// ---------------- launch ----------------
extern "C" void kernel_launch(void* const* d_in, const int* in_sizes, int n_in,
                              void* d_out, int out_size) {
    const float* x   = (const float*)d_in[0];
    const float* Uu  = (const float*)d_in[1];
    const float* Ur  = (const float*)d_in[2];
    const float* U   = (const float*)d_in[3];
    const float* Wu  = (const float*)d_in[4];
    const float* Wr  = (const float*)d_in[5];
    const float* W   = (const float*)d_in[6];
    const float* Bu  = (const float*)d_in[7];
    const float* Br  = (const float*)d_in[8];
    const float* B   = (const float*)d_in[9];
    const float* Uhr = (const float*)d_in[10];
    const float* Uh  = (const float*)d_in[11];
    float* out = (float*)d_out;

    float *Zu, *Zr, *Zc, *Hb;
    int* ct;
    cudaGetSymbolAddress((void**)&Zu, g_Zu);
    cudaGetSymbolAddress((void**)&Zr, g_Zr);
    cudaGetSymbolAddress((void**)&Zc, g_Zc);
    cudaGetSymbolAddress((void**)&Hb, g_H);
    cudaGetSymbolAddress((void**)&ct, g_ctr);

    cudaFuncSetAttribute(quad_scan, cudaFuncAttributeMaxDynamicSharedMemorySize,
                         SMEM_TOTAL_Q);

    reset_ctrs_kernel<<<(4 * NSLOT * CSTRIDE + 255) / 256, 256>>>();

    {   // layer 0 input projections
        dim3 gg(HID / 128, SEQ / 128, 3);
        GemmJob A0{x, Uu, Zu}, B0{x, Ur, Zr}, C0{x, U, Zc};
        sgemm_nt_batch<<<gg, 256>>>(A0, B0, C0);
    }

    QuadArgs q;
    q.Wu = Wu; q.Wr = Wr; q.Wc = W;
    q.Bu = Bu; q.Br = Br; q.Bc = B;
    q.Uh = Uh; q.Uhr = Uhr;
    q.Zu = Zu; q.Zr = Zr; q.Zc = Zc;
    q.H = Hb; q.out = out; q.ctr = ct;
    quad_scan<<<NCTA, 512, SMEM_TOTAL_Q>>>(q);

    (void)in_sizes; (void)n_in; (void)out_size;
}

// round 12
// speedup vs baseline: 2.3338x; 1.1082x over previous
#include <cuda_runtime.h>
#include <cuda_fp16.h>

#define SEQ 4096
#define HID 1024
#define NCTA 128
#define CSTRIDE 32
#define NSLOT 16
#define NCH 9            // chains per warp; 16 warps x 9 = 144 chains

// ---------------- device scratch ----------------
__device__ float g_Zu[SEQ * HID];
__device__ float g_Zr[SEQ * HID];
__device__ float g_Zc[SEQ * HID];
__device__ float g_H[4][SEQ * HID];
__device__ int   g_ctr[4][NSLOT * CSTRIDE];

__global__ void reset_ctrs_kernel() {
    int i = blockIdx.x * blockDim.x + threadIdx.x;
    if (i < 4 * NSLOT * CSTRIDE) ((int*)g_ctr)[i] = 0;
}

// ---------------- memory helpers (proven R7 sync primitives) ----------------
__device__ __forceinline__ float4 ldcg4(const float* p) {
    float4 v;
    asm volatile("ld.global.cg.v4.f32 {%0,%1,%2,%3},[%4];"
                 : "=f"(v.x), "=f"(v.y), "=f"(v.z), "=f"(v.w) : "l"(p) : "memory");
    return v;
}
__device__ __forceinline__ void stcg(float* p, float v) {
    asm volatile("st.global.cg.f32 [%0],%1;" :: "l"(p), "f"(v) : "memory");
}
__device__ __forceinline__ int ldacq(const int* p) {
    int v;
    asm volatile("ld.acquire.gpu.global.s32 %0,[%1];" : "=r"(v) : "l"(p) : "memory");
    return v;
}
__device__ __forceinline__ void red_release_add(int* p, int v) {
    asm volatile("red.release.gpu.global.add.s32 [%0],%1;" :: "l"(p), "r"(v) : "memory");
}
__device__ __forceinline__ float sigf(float x) { return 1.f / (1.f + __expf(-x)); }

// pack two floats to one half2 stored as uint (trivially copyable carriers)
__device__ __forceinline__ unsigned pack_h2(float a, float b) {
    __half2 h = __floats2half2_rn(a, b);
    return *(unsigned*)&h;
}

// fp16 SIMD dot of 8 elems (two uint4 = 4 half2 each), fp32 result.
__device__ __forceinline__ float dot4u(const uint4& wv, const uint4& hv) {
    const __half2* w = (const __half2*)&wv;
    const __half2* h = (const __half2*)&hv;
    __half2 acc = __hmul2(w[0], h[0]);
    acc = __hfma2(w[1], h[1], acc);
    acc = __hfma2(w[2], h[2], acc);
    acc = __hfma2(w[3], h[3], acc);
    float2 f = __half22float2(acc);
    return f.x + f.y;
}

// ---------------- fp32 SGEMM batch (layer-0 input projections) -------------
struct GemmJob { const float* A; const float* B; float* C; };
__global__ __launch_bounds__(256) void sgemm_nt_batch(GemmJob j0, GemmJob j1, GemmJob j2) {
    const GemmJob job = (blockIdx.z == 0) ? j0 : (blockIdx.z == 1) ? j1 : j2;
    const float* __restrict__ A = job.A;
    const float* __restrict__ B = job.B;
    float* __restrict__ C = job.C;
    const int K = HID, N = HID;
    __shared__ float As[8][128];
    __shared__ float Bs[8][128];
    const int tid = threadIdx.x;
    const int m0 = blockIdx.y * 128;
    const int n0 = blockIdx.x * 128;
    const int tx = tid & 15;
    const int ty = tid >> 4;
    const int lrow = tid >> 1;
    const int kp = (tid & 1) * 4;

    const float* Ap = A + (m0 + lrow) * K + kp;
    const float* Bp = B + (n0 + lrow) * K + kp;

    float acc[8][8];
#pragma unroll
    for (int i = 0; i < 8; i++)
#pragma unroll
        for (int j = 0; j < 8; j++) acc[i][j] = 0.f;

    for (int k0 = 0; k0 < K; k0 += 8) {
        float4 av = *(const float4*)(Ap + k0);
        float4 bv = *(const float4*)(Bp + k0);
        __syncthreads();
        As[kp + 0][lrow] = av.x; As[kp + 1][lrow] = av.y;
        As[kp + 2][lrow] = av.z; As[kp + 3][lrow] = av.w;
        Bs[kp + 0][lrow] = bv.x; Bs[kp + 1][lrow] = bv.y;
        Bs[kp + 2][lrow] = bv.z; Bs[kp + 3][lrow] = bv.w;
        __syncthreads();
#pragma unroll
        for (int kk = 0; kk < 8; kk++) {
            float a[8], b[8];
#pragma unroll
            for (int i = 0; i < 8; i++) a[i] = As[kk][ty * 8 + i];
#pragma unroll
            for (int j = 0; j < 8; j++) b[j] = Bs[kk][tx * 8 + j];
#pragma unroll
            for (int i = 0; i < 8; i++)
#pragma unroll
                for (int j = 0; j < 8; j++) acc[i][j] = fmaf(a[i], b[j], acc[i][j]);
        }
    }
#pragma unroll
    for (int i = 0; i < 8; i++) {
        float* Cp = C + (m0 + ty * 8 + i) * N + n0 + tx * 8;
#pragma unroll
        for (int j = 0; j < 8; j++) Cp[j] = acc[i][j];
    }
}

// ---------------- quad-layer fused GRU scan ----------------
// 128 CTAs x 512 threads (16 warps). Chain c (0..143) ordered by input vector
// v: [0,40) h0 = L0 rec(24)+L1 s,q(16); [40,80) h1; [80,120) h2; [120,144) h3
// = L3 rec. Warp w owns chains [9w, 9w+9): first 3 in regs (uint4 x4), 6 in
// SMEM fp16. Round R: layer l computes t=R-l. Warps 0-3 poll+stage
// h_l(R-1-l) into fp16 SMEM; barA; chains + shfl reduce -> res[]; barB;
// warp 15 lane i = instance (l=i>>3, j=i&7) does gates + st.cg + release.
// SMEM layouts (h and weights) are transposed: group (L,q) at q*512 + L*16
// -> every LDS.128/STS.128 is conflict-free (R11 had 16-way conflicts on h).
struct QuadArgs {
    const float *Wu, *Wr, *Wc, *Bu, *Br, *Bc, *Uh, *Uhr, *Zu, *Zr, *Zc;
    float *H, *out;
    int *ctr;
};

#define WROW_BYTES (96 * 2048)
#define HBUF_BYTES (4 * 2048)
#define SMEM_TOTAL_Q (WROW_BYTES + HBUF_BYTES + 160 * 4)

__global__ __launch_bounds__(512, 1) void quad_scan(QuadArgs a) {
    extern __shared__ char smem[];
    char* wrow_b = smem;
    char* hbuf_b = smem + WROW_BYTES;
    float* res   = (float*)(smem + WROW_BYTES + HBUF_BYTES);

    const int tid = threadIdx.x;
    const int w = tid >> 5, L = tid & 31;
    const int bid = blockIdx.x;
    const size_t HH = (size_t)HID * HID;

    // majority input vector for this warp = vector of middle chain
    const int c4 = w * NCH + 4;
    const int vMaj = (c4 < 40) ? 0 : (c4 < 80) ? 1 : (c4 < 120) ? 2 : 3;

    uint4 wreg[3][4];
    int meta[NCH];

    // ---- init: resolve chains, convert weights to fp16 (regs / SMEM) ----
#pragma unroll
    for (int k = 0; k < NCH; k++) {
        const int c = w * NCH + k;
        const int v = (c < 40) ? 0 : (c < 80) ? 1 : (c < 120) ? 2 : 3;
        const int g = c - 40 * v;
        int l, j, kind;
        if (v == 3 || g < 24) { l = v; j = g / 3; kind = g - 3 * j; }
        else { const int gg = g - 24; l = v + 1; j = gg >> 1; kind = 3 + (gg & 1); }
        const int jf = (bid << 3) + j;
        const float* wp;
        if (kind == 0)      wp = a.Wu  + (size_t)l * HH + (size_t)jf * HID;
        else if (kind == 1) wp = a.Wr  + (size_t)l * HH + (size_t)jf * HID;
        else if (kind == 2) wp = a.Wc  + (size_t)l * HH + (size_t)jf * HID;
        else if (kind == 3) wp = a.Uh  + (size_t)(l - 1) * HH + (size_t)jf * HID;
        else                wp = a.Uhr + (size_t)(l - 1) * HH + (size_t)jf * HID;
        const int roff = (l * 8 + j) * 5 + kind;
        meta[k] = l | (((v == vMaj) ? 1 : 0) << 2) | (v << 3) | (roff << 5);

        unsigned tmp[16];
        const float* rp = wp + 32 * L;
#pragma unroll
        for (int i = 0; i < 8; i++) {
            float4 f = __ldg((const float4*)rp + i);
            tmp[2 * i]     = pack_h2(f.x, f.y);
            tmp[2 * i + 1] = pack_h2(f.z, f.w);
        }
        if (k < 3) {
#pragma unroll
            for (int q = 0; q < 4; q++)
                wreg[k][q] = make_uint4(tmp[4 * q], tmp[4 * q + 1],
                                        tmp[4 * q + 2], tmp[4 * q + 3]);
        } else {
            char* rb = wrow_b + (size_t)(w * 6 + (k - 3)) * 2048;
#pragma unroll
            for (int q = 0; q < 4; q++)
                *(uint4*)(rb + q * 512 + L * 16) =
                    make_uint4(tmp[4 * q], tmp[4 * q + 1],
                               tmp[4 * q + 2], tmp[4 * q + 3]);
        }
    }

    // gate-lane state (warp 15, lane = instance)
    float hj = 0.f, bu = 0.f, br = 0.f, bc = 0.f;
    int gl = 0, gj = 0;
    if (w == 15) {
        gl = L >> 3; gj = (bid << 3) + (L & 7);
        bu = a.Bu[gl * HID + gj]; br = a.Br[gl * HID + gj]; bc = a.Bc[gl * HID + gj];
    }
    __syncthreads();

    for (int R = 0; R < SEQ + 3; R++) {
        // prefetch layer-0 gate input terms (hidden under staging)
        float zu = 0.f, zr = 0.f, zc = 0.f;
        if (w == 15 && gl == 0 && R < SEQ) {
            zu = __ldg(a.Zu + (size_t)R * HID + gj);
            zr = __ldg(a.Zr + (size_t)R * HID + gj);
            zc = __ldg(a.Zc + (size_t)R * HID + gj);
        }
        // stage: warp l brings h_l(R-1-l) into fp16 SMEM (transposed layout)
        if (w < 4) {
            const int l = w;
            char* hb = hbuf_b + l * 2048;
            if (R >= l + 1) {
                int row = R - 1 - l; if (row > SEQ - 1) row = SEQ - 1;
                int tgt = R - l;     if (tgt > SEQ) tgt = SEQ;
                tgt *= 64;
                if (L < NSLOT) {
                    const int* cp = a.ctr + l * (NSLOT * CSTRIDE) + L * CSTRIDE;
                    while (ldacq(cp) < tgt) { }
                }
                __syncwarp();
                const float* hr = a.H + ((size_t)l * SEQ + row) * HID + 32 * L;
                unsigned hv[16];
#pragma unroll
                for (int i = 0; i < 8; i++) {
                    float4 f = ldcg4(hr + 4 * i);
                    hv[2 * i]     = pack_h2(f.x, f.y);
                    hv[2 * i + 1] = pack_h2(f.z, f.w);
                }
#pragma unroll
                for (int q = 0; q < 4; q++)
                    *(uint4*)(hb + q * 512 + L * 16) =
                        make_uint4(hv[4 * q], hv[4 * q + 1],
                                   hv[4 * q + 2], hv[4 * q + 3]);
            } else {
                const uint4 z = make_uint4(0, 0, 0, 0);
#pragma unroll
                for (int q = 0; q < 4; q++) *(uint4*)(hb + q * 512 + L * 16) = z;
            }
        }
        __syncthreads();   // bar A: all 4 staged vectors ready

        // cache majority vector in regs (conflict-free reads)
        uint4 hc[4];
#pragma unroll
        for (int q = 0; q < 4; q++)
            hc[q] = *(const uint4*)(hbuf_b + vMaj * 2048 + q * 512 + L * 16);

        // chains
#pragma unroll
        for (int k = 0; k < NCH; k++) {
            const int m = meta[k];
            const int l = m & 3;
            const int t = R - l;
            if (t < 0 || t >= SEQ) continue;
            const bool cached = (m >> 2) & 1;
            const int v = (m >> 3) & 3;
            float s = 0.f;
#pragma unroll
            for (int q = 0; q < 4; q++) {
                uint4 hg;
                if (cached) hg = hc[q];
                else hg = *(const uint4*)(hbuf_b + v * 2048 + q * 512 + L * 16);
                uint4 wg;
                if (k < 3) wg = wreg[k][q];
                else wg = *(const uint4*)(wrow_b + (size_t)(w * 6 + (k - 3)) * 2048 + q * 512 + L * 16);
                s += dot4u(wg, hg);
            }
#pragma unroll
            for (int off = 16; off > 0; off >>= 1)
                s += __shfl_xor_sync(0xffffffffu, s, off);
            if (L == 0) res[m >> 5] = s;
        }
        __syncthreads();   // bar B: res[] complete

        // gates: warp 15, lane = instance (l = L>>3, j = L&7)
        if (w == 15) {
            const int t = R - gl;
            if (t >= 0 && t < SEQ) {
                const float r0 = res[L * 5 + 0], r1 = res[L * 5 + 1], r2 = res[L * 5 + 2];
                float u, r, c;
                if (gl == 0) {
                    u = sigf(r0 + zu + bu);
                    r = sigf(r1 + zr + br);
                    c = sigf(zc + r * r2 + bc);
                } else {
                    const float s5 = res[L * 5 + 3], q5 = res[L * 5 + 4];
                    u = sigf(s5 + r0 + bu);       // shared Uh term feeds u...
                    r = sigf(q5 + r1 + br);
                    c = sigf(s5 + r * r2 + bc);   // ...and c (aliased parameter)
                }
                hj = fmaf(u, hj - c, c);
                stcg(a.H + ((size_t)gl * SEQ + t) * HID + gj, hj);
                red_release_add(a.ctr + gl * (NSLOT * CSTRIDE) + (bid & (NSLOT - 1)) * CSTRIDE, 1);
                if (t == SEQ - 1) a.out[gl * HID + gj] = hj;
            }
        }
    }
}

// ---------------- launch ----------------
extern "C" void kernel_launch(void* const* d_in, const int* in_sizes, int n_in,
                              void* d_out, int out_size) {
    const float* x   = (const float*)d_in[0];
    const float* Uu  = (const float*)d_in[1];
    const float* Ur  = (const float*)d_in[2];
    const float* U   = (const float*)d_in[3];
    const float* Wu  = (const float*)d_in[4];
    const float* Wr  = (const float*)d_in[5];
    const float* W   = (const float*)d_in[6];
    const float* Bu  = (const float*)d_in[7];
    const float* Br  = (const float*)d_in[8];
    const float* B   = (const float*)d_in[9];
    const float* Uhr = (const float*)d_in[10];
    const float* Uh  = (const float*)d_in[11];
    float* out = (float*)d_out;

    float *Zu, *Zr, *Zc, *Hb;
    int* ct;
    cudaGetSymbolAddress((void**)&Zu, g_Zu);
    cudaGetSymbolAddress((void**)&Zr, g_Zr);
    cudaGetSymbolAddress((void**)&Zc, g_Zc);
    cudaGetSymbolAddress((void**)&Hb, g_H);
    cudaGetSymbolAddress((void**)&ct, g_ctr);

    cudaFuncSetAttribute(quad_scan, cudaFuncAttributeMaxDynamicSharedMemorySize,
                         SMEM_TOTAL_Q);

    reset_ctrs_kernel<<<(4 * NSLOT * CSTRIDE + 255) / 256, 256>>>();

    {   // layer 0 input projections
        dim3 gg(HID / 128, SEQ / 128, 3);
        GemmJob A0{x, Uu, Zu}, B0{x, Ur, Zr}, C0{x, U, Zc};
        sgemm_nt_batch<<<gg, 256>>>(A0, B0, C0);
    }

    QuadArgs q;
    q.Wu = Wu; q.Wr = Wr; q.Wc = W;
    q.Bu = Bu; q.Br = Br; q.Bc = B;
    q.Uh = Uh; q.Uhr = Uhr;
    q.Zu = Zu; q.Zr = Zr; q.Zc = Zc;
    q.H = Hb; q.out = out; q.ctr = ct;
    quad_scan<<<NCTA, 512, SMEM_TOTAL_Q>>>(q);

    (void)in_sizes; (void)n_in; (void)out_size;
}

// round 13
// speedup vs baseline: 3.0195x; 1.2938x over previous
#include <cuda_runtime.h>
#include <cuda_fp16.h>

#define SEQ 4096
#define HID 1024
#define NCTA 128
#define CSTRIDE 32
#define NSLOT 16
#define NCH 9            // chains per warp; 16 warps x 9 = 144 chains
#define NREG 4           // register-resident chains per warp (rest in SMEM)

// ---------------- device scratch ----------------
__device__ float  g_Zu[SEQ * HID];
__device__ float  g_Zr[SEQ * HID];
__device__ float  g_Zc[SEQ * HID];
__device__ __half g_Hh[4][SEQ * HID];      // fp16 hidden-state exchange
__device__ int    g_ctr[4][NSLOT * CSTRIDE];

__global__ void reset_ctrs_kernel() {
    int i = blockIdx.x * blockDim.x + threadIdx.x;
    if (i < 4 * NSLOT * CSTRIDE) ((int*)g_ctr)[i] = 0;
}

// ---------------- memory helpers (proven sync primitives) ----------------
__device__ __forceinline__ uint4 ldcg4u(const uint4* p) {
    uint4 v;
    asm volatile("ld.global.cg.v4.u32 {%0,%1,%2,%3},[%4];"
                 : "=r"(v.x), "=r"(v.y), "=r"(v.z), "=r"(v.w) : "l"(p) : "memory");
    return v;
}
__device__ __forceinline__ void stcg_h(__half* p, __half v) {
    unsigned short b = *(unsigned short*)&v;
    asm volatile("st.global.cg.u16 [%0],%1;" :: "l"(p), "h"(b) : "memory");
}
__device__ __forceinline__ int ldacq(const int* p) {
    int v;
    asm volatile("ld.acquire.gpu.global.s32 %0,[%1];" : "=r"(v) : "l"(p) : "memory");
    return v;
}
__device__ __forceinline__ void red_release_add(int* p, int v) {
    asm volatile("red.release.gpu.global.add.s32 [%0],%1;" :: "l"(p), "r"(v) : "memory");
}
__device__ __forceinline__ float sigf(float x) { return 1.f / (1.f + __expf(-x)); }

__device__ __forceinline__ unsigned pack_h2(float a, float b) {
    __half2 h = __floats2half2_rn(a, b);
    return *(unsigned*)&h;
}
// fp16 SIMD dot of 8 elems, fp32 result
__device__ __forceinline__ float dot4u(const uint4& wv, const uint4& hv) {
    const __half2* w = (const __half2*)&wv;
    const __half2* h = (const __half2*)&hv;
    __half2 acc = __hmul2(w[0], h[0]);
    acc = __hfma2(w[1], h[1], acc);
    acc = __hfma2(w[2], h[2], acc);
    acc = __hfma2(w[3], h[3], acc);
    float2 f = __half22float2(acc);
    return f.x + f.y;
}

// ---------------- fp32 SGEMM batch (layer-0 input projections) -------------
struct GemmJob { const float* A; const float* B; float* C; };
__global__ __launch_bounds__(256) void sgemm_nt_batch(GemmJob j0, GemmJob j1, GemmJob j2) {
    const GemmJob job = (blockIdx.z == 0) ? j0 : (blockIdx.z == 1) ? j1 : j2;
    const float* __restrict__ A = job.A;
    const float* __restrict__ B = job.B;
    float* __restrict__ C = job.C;
    const int K = HID, N = HID;
    __shared__ float As[8][128];
    __shared__ float Bs[8][128];
    const int tid = threadIdx.x;
    const int m0 = blockIdx.y * 128;
    const int n0 = blockIdx.x * 128;
    const int tx = tid & 15;
    const int ty = tid >> 4;
    const int lrow = tid >> 1;
    const int kp = (tid & 1) * 4;

    const float* Ap = A + (m0 + lrow) * K + kp;
    const float* Bp = B + (n0 + lrow) * K + kp;

    float acc[8][8];
#pragma unroll
    for (int i = 0; i < 8; i++)
#pragma unroll
        for (int j = 0; j < 8; j++) acc[i][j] = 0.f;

    for (int k0 = 0; k0 < K; k0 += 8) {
        float4 av = *(const float4*)(Ap + k0);
        float4 bv = *(const float4*)(Bp + k0);
        __syncthreads();
        As[kp + 0][lrow] = av.x; As[kp + 1][lrow] = av.y;
        As[kp + 2][lrow] = av.z; As[kp + 3][lrow] = av.w;
        Bs[kp + 0][lrow] = bv.x; Bs[kp + 1][lrow] = bv.y;
        Bs[kp + 2][lrow] = bv.z; Bs[kp + 3][lrow] = bv.w;
        __syncthreads();
#pragma unroll
        for (int kk = 0; kk < 8; kk++) {
            float a[8], b[8];
#pragma unroll
            for (int i = 0; i < 8; i++) a[i] = As[kk][ty * 8 + i];
#pragma unroll
            for (int j = 0; j < 8; j++) b[j] = Bs[kk][tx * 8 + j];
#pragma unroll
            for (int i = 0; i < 8; i++)
#pragma unroll
                for (int j = 0; j < 8; j++) acc[i][j] = fmaf(a[i], b[j], acc[i][j]);
        }
    }
#pragma unroll
    for (int i = 0; i < 8; i++) {
        float* Cp = C + (m0 + ty * 8 + i) * N + n0 + tx * 8;
#pragma unroll
        for (int j = 0; j < 8; j++) Cp[j] = acc[i][j];
    }
}

// ---------------- quad-layer fused GRU scan ----------------
// 128 CTAs x 512 threads (16 warps), 9 chains/warp: first NREG=4 in regs,
// 5 in SMEM fp16 (transposed conflict-free layout q*512+L*16).
// Round R: layer l computes t=R-l. Warps 0-3 poll + RAW-copy fp16 h rows
// into SMEM; barA; chains (dot + 3-shfl reduce -> 4 partials in res4); barB;
// warp 15 lane i = instance (l=i>>3,j=i&7): sum partials, gates, fp16 store.
struct QuadArgs {
    const float *Wu, *Wr, *Wc, *Bu, *Br, *Bc, *Uh, *Uhr, *Zu, *Zr, *Zc;
    __half *H;
    float *out;
    int *ctr;
};

#define WROW_BYTES (80 * 2048)
#define HBUF_BYTES (4 * 2048)
#define RES4_BYTES (160 * 4 * 4)
#define SMEM_TOTAL_Q (WROW_BYTES + HBUF_BYTES + RES4_BYTES)

__global__ __launch_bounds__(512, 1) void quad_scan(QuadArgs a) {
    extern __shared__ char smem[];
    char*  wrow_b = smem;
    char*  hbuf_b = smem + WROW_BYTES;
    float* res4   = (float*)(smem + WROW_BYTES + HBUF_BYTES);

    const int tid = threadIdx.x;
    const int w = tid >> 5, L = tid & 31;
    const int bid = blockIdx.x;
    const size_t HH = (size_t)HID * HID;

    const int c4 = w * NCH + 4;
    const int vMaj = (c4 < 40) ? 0 : (c4 < 80) ? 1 : (c4 < 120) ? 2 : 3;

    uint4 wreg[NREG][4];
    int meta[NCH];

    // ---- init: resolve chains, convert weights to fp16 (regs / SMEM) ----
#pragma unroll
    for (int k = 0; k < NCH; k++) {
        const int c = w * NCH + k;
        const int v = (c < 40) ? 0 : (c < 80) ? 1 : (c < 120) ? 2 : 3;
        const int g = c - 40 * v;
        int l, j, kind;
        if (v == 3 || g < 24) { l = v; j = g / 3; kind = g - 3 * j; }
        else { const int gg = g - 24; l = v + 1; j = gg >> 1; kind = 3 + (gg & 1); }
        const int jf = (bid << 3) + j;
        const float* wp;
        if (kind == 0)      wp = a.Wu  + (size_t)l * HH + (size_t)jf * HID;
        else if (kind == 1) wp = a.Wr  + (size_t)l * HH + (size_t)jf * HID;
        else if (kind == 2) wp = a.Wc  + (size_t)l * HH + (size_t)jf * HID;
        else if (kind == 3) wp = a.Uh  + (size_t)(l - 1) * HH + (size_t)jf * HID;
        else                wp = a.Uhr + (size_t)(l - 1) * HH + (size_t)jf * HID;
        const int roff = (l * 8 + j) * 5 + kind;
        meta[k] = l | (((v == vMaj) ? 1 : 0) << 2) | (v << 3) | (roff << 5);

        unsigned tmp[16];
        const float* rp = wp + 32 * L;
#pragma unroll
        for (int i = 0; i < 8; i++) {
            float4 f = __ldg((const float4*)rp + i);
            tmp[2 * i]     = pack_h2(f.x, f.y);
            tmp[2 * i + 1] = pack_h2(f.z, f.w);
        }
        if (k < NREG) {
#pragma unroll
            for (int q = 0; q < 4; q++)
                wreg[k][q] = make_uint4(tmp[4 * q], tmp[4 * q + 1],
                                        tmp[4 * q + 2], tmp[4 * q + 3]);
        } else {
            char* rb = wrow_b + (size_t)(w * 5 + (k - NREG)) * 2048;
#pragma unroll
            for (int q = 0; q < 4; q++)
                *(uint4*)(rb + q * 512 + L * 16) =
                    make_uint4(tmp[4 * q], tmp[4 * q + 1],
                               tmp[4 * q + 2], tmp[4 * q + 3]);
        }
    }

    // gate-lane state (warp 15, lane = instance)
    float hj = 0.f, bu = 0.f, br = 0.f, bc = 0.f;
    int gl = 0, gj = 0;
    if (w == 15) {
        gl = L >> 3; gj = (bid << 3) + (L & 7);
        bu = a.Bu[gl * HID + gj]; br = a.Br[gl * HID + gj]; bc = a.Bc[gl * HID + gj];
    }
    __syncthreads();

    for (int R = 0; R < SEQ + 3; R++) {
        float zu = 0.f, zr = 0.f, zc = 0.f;
        if (w == 15 && gl == 0 && R < SEQ) {
            zu = __ldg(a.Zu + (size_t)R * HID + gj);
            zr = __ldg(a.Zr + (size_t)R * HID + gj);
            zc = __ldg(a.Zc + (size_t)R * HID + gj);
        }
        // stage: warp l RAW-copies fp16 row h_l(R-1-l) into transposed SMEM
        if (w < 4) {
            const int l = w;
            char* hb = hbuf_b + l * 2048;
            if (R >= l + 1) {
                int row = R - 1 - l; if (row > SEQ - 1) row = SEQ - 1;
                int tgt = R - l;     if (tgt > SEQ) tgt = SEQ;
                tgt *= 64;
                if (L < NSLOT) {
                    const int* cp = a.ctr + l * (NSLOT * CSTRIDE) + L * CSTRIDE;
                    while (ldacq(cp) < tgt) { }
                }
                __syncwarp();
                // fp16 row = 2KB; lane L holds bytes [L*64, L*64+64) = elements
                // 32L+8q+0..7 per uint4 q -> maps EXACTLY to q*512 + L*16.
                const uint4* hr = (const uint4*)(a.H + ((size_t)l * SEQ + row) * HID) + L * 4;
                uint4 hv0 = ldcg4u(hr + 0);
                uint4 hv1 = ldcg4u(hr + 1);
                uint4 hv2 = ldcg4u(hr + 2);
                uint4 hv3 = ldcg4u(hr + 3);
                *(uint4*)(hb + 0 * 512 + L * 16) = hv0;
                *(uint4*)(hb + 1 * 512 + L * 16) = hv1;
                *(uint4*)(hb + 2 * 512 + L * 16) = hv2;
                *(uint4*)(hb + 3 * 512 + L * 16) = hv3;
            } else {
                const uint4 z = make_uint4(0, 0, 0, 0);
#pragma unroll
                for (int q = 0; q < 4; q++) *(uint4*)(hb + q * 512 + L * 16) = z;
            }
        }
        __syncthreads();   // bar A

        uint4 hc[4];
#pragma unroll
        for (int q = 0; q < 4; q++)
            hc[q] = *(const uint4*)(hbuf_b + vMaj * 2048 + q * 512 + L * 16);

        // chains: dot + 3-shfl partial reduce (lane class L&3)
#pragma unroll
        for (int k = 0; k < NCH; k++) {
            const int m = meta[k];
            const int l = m & 3;
            const int t = R - l;
            if (t < 0 || t >= SEQ) continue;
            const bool cached = (m >> 2) & 1;
            const int v = (m >> 3) & 3;
            float s = 0.f;
#pragma unroll
            for (int q = 0; q < 4; q++) {
                uint4 hg;
                if (cached) hg = hc[q];
                else hg = *(const uint4*)(hbuf_b + v * 2048 + q * 512 + L * 16);
                uint4 wg;
                if (k < NREG) wg = wreg[k][q];
                else wg = *(const uint4*)(wrow_b + (size_t)(w * 5 + (k - NREG)) * 2048 + q * 512 + L * 16);
                s += dot4u(wg, hg);
            }
            s += __shfl_xor_sync(0xffffffffu, s, 16);
            s += __shfl_xor_sync(0xffffffffu, s, 8);
            s += __shfl_xor_sync(0xffffffffu, s, 4);
            if (L < 4) res4[(m >> 5) * 4 + L] = s;
        }
        __syncthreads();   // bar B

        // gates: warp 15, lane = instance
        if (w == 15) {
            const int t = R - gl;
            if (t >= 0 && t < SEQ) {
                const float4 p0 = *(const float4*)(res4 + (L * 5 + 0) * 4);
                const float4 p1 = *(const float4*)(res4 + (L * 5 + 1) * 4);
                const float4 p2 = *(const float4*)(res4 + (L * 5 + 2) * 4);
                const float r0 = (p0.x + p0.y) + (p0.z + p0.w);
                const float r1 = (p1.x + p1.y) + (p1.z + p1.w);
                const float r2 = (p2.x + p2.y) + (p2.z + p2.w);
                float u, r, c;
                if (gl == 0) {
                    u = sigf(r0 + zu + bu);
                    r = sigf(r1 + zr + br);
                    c = sigf(zc + r * r2 + bc);
                } else {
                    const float4 p3 = *(const float4*)(res4 + (L * 5 + 3) * 4);
                    const float4 p4 = *(const float4*)(res4 + (L * 5 + 4) * 4);
                    const float s5 = (p3.x + p3.y) + (p3.z + p3.w);
                    const float q5 = (p4.x + p4.y) + (p4.z + p4.w);
                    u = sigf(s5 + r0 + bu);       // shared Uh term feeds u...
                    r = sigf(q5 + r1 + br);
                    c = sigf(s5 + r * r2 + bc);   // ...and c (aliased parameter)
                }
                hj = fmaf(u, hj - c, c);
                stcg_h(a.H + ((size_t)gl * SEQ + t) * HID + gj, __float2half_rn(hj));
                red_release_add(a.ctr + gl * (NSLOT * CSTRIDE) + (bid & (NSLOT - 1)) * CSTRIDE, 1);
                if (t == SEQ - 1) a.out[gl * HID + gj] = hj;
            }
        }
    }
}

// ---------------- launch ----------------
extern "C" void kernel_launch(void* const* d_in, const int* in_sizes, int n_in,
                              void* d_out, int out_size) {
    const float* x   = (const float*)d_in[0];
    const float* Uu  = (const float*)d_in[1];
    const float* Ur  = (const float*)d_in[2];
    const float* U   = (const float*)d_in[3];
    const float* Wu  = (const float*)d_in[4];
    const float* Wr  = (const float*)d_in[5];
    const float* W   = (const float*)d_in[6];
    const float* Bu  = (const float*)d_in[7];
    const float* Br  = (const float*)d_in[8];
    const float* B   = (const float*)d_in[9];
    const float* Uhr = (const float*)d_in[10];
    const float* Uh  = (const float*)d_in[11];
    float* out = (float*)d_out;

    float *Zu, *Zr, *Zc;
    __half* Hh;
    int* ct;
    cudaGetSymbolAddress((void**)&Zu, g_Zu);
    cudaGetSymbolAddress((void**)&Zr, g_Zr);
    cudaGetSymbolAddress((void**)&Zc, g_Zc);
    cudaGetSymbolAddress((void**)&Hh, g_Hh);
    cudaGetSymbolAddress((void**)&ct, g_ctr);

    cudaFuncSetAttribute(quad_scan, cudaFuncAttributeMaxDynamicSharedMemorySize,
                         SMEM_TOTAL_Q);

    reset_ctrs_kernel<<<(4 * NSLOT * CSTRIDE + 255) / 256, 256>>>();

    {   // layer 0 input projections
        dim3 gg(HID / 128, SEQ / 128, 3);
        GemmJob A0{x, Uu, Zu}, B0{x, Ur, Zr}, C0{x, U, Zc};
        sgemm_nt_batch<<<gg, 256>>>(A0, B0, C0);
    }

    QuadArgs q;
    q.Wu = Wu; q.Wr = Wr; q.Wc = W;
    q.Bu = Bu; q.Br = Br; q.Bc = B;
    q.Uh = Uh; q.Uhr = Uhr;
    q.Zu = Zu; q.Zr = Zr; q.Zc = Zc;
    q.H = Hh; q.out = out; q.ctr = ct;
    quad_scan<<<NCTA, 512, SMEM_TOTAL_Q>>>(q);

    (void)in_sizes; (void)n_in; (void)out_size;
}